// round 2
// baseline (speedup 1.0000x reference)
#include <cuda_runtime.h>

// Fused shift + grouped conv(H taps) + grouped conv(W taps).
// x:  (1,512,14,14) fp32, channel c = i*8 + o   (i=0..63, o=0..7)
// w1: (16,64,3)  -> y[k,o,h,w] = sum_{i,j} xr[i,o,h-1+j,w] * w1[k,i,j]
//     where xr[h'] = x[(h'-1) mod 14]  (roll +1 along H), taps zero-padded.
// w2: (32,8,3)   -> out[(i2*16+k)*196 + h*14 + w] =
//     sum_{o,t} y[k,o,h,w-1+t] * w2[i2,o,t]   (zero pad along W)
//
// One CTA per (k-quad, h): grid (4,14), 128 threads.

__global__ void __launch_bounds__(128) fused_kernel(
    const float* __restrict__ x,
    const float* __restrict__ w1,
    const float* __restrict__ w2,
    float* __restrict__ out)
{
    __shared__ __align__(16) float ws1[64 * 3 * 4];  // [i][j][k_local]
    __shared__ float ys[4 * 8 * 15];                 // [k_local][o][w, pad to 15]

    const int kq  = blockIdx.x;   // 0..3  (k-quad)
    const int h   = blockIdx.y;   // 0..13
    const int tid = threadIdx.x;

    // ---- preload w2 row for this thread's i2 (stage-2 weights) ----
    const int i2  = tid >> 2;     // 0..31
    const int kl2 = tid & 3;      // 0..3
    float wr[24];
    {
        const float4* p = (const float4*)(w2 + i2 * 24);  // 96B, 16B aligned
        #pragma unroll
        for (int q = 0; q < 6; q++) {
            float4 v = __ldg(p + q);
            wr[q * 4 + 0] = v.x; wr[q * 4 + 1] = v.y;
            wr[q * 4 + 2] = v.z; wr[q * 4 + 3] = v.w;
        }
    }

    // ---- stage w1 for this k-quad into smem: ws1[(i*3+j)*4 + kl] ----
    for (int idx = tid; idx < 768; idx += 128) {
        int kl = idx & 3;
        int ij = idx >> 2;            // i*3 + j
        int i  = ij / 3, j = ij - i * 3;
        ws1[idx] = __ldg(w1 + ((kq * 4 + kl) * 64 + i) * 3 + j);
    }
    __syncthreads();

    // ---- stage 1: 112 threads, each (o,w) computes 4 k accumulators ----
    if (tid < 112) {
        const int o = tid / 14;
        const int w = tid - o * 14;

        // tap j source row r_j = (h + j - 2) mod 14 ; validity of tap
        const int  r0 = (h + 12) % 14;     // j=0, valid if h >= 1
        const int  r1 = (h + 13) % 14;     // j=1, always valid
        const int  r2 = h;                 // j=2, valid if h <= 12
        const bool v0 = (h >= 1);
        const bool v2 = (h <= 12);

        const float* p0 = x + o * 196 + r0 * 14 + w;
        const float* p1 = x + o * 196 + r1 * 14 + w;
        const float* p2 = x + o * 196 + r2 * 14 + w;

        float a0 = 0.f, a1 = 0.f, a2 = 0.f, a3 = 0.f;
        #pragma unroll 8
        for (int i = 0; i < 64; i++) {
            const int off = i * 1568;          // (i*8)*196
            float x0 = v0 ? __ldg(p0 + off) : 0.f;
            float x1 =      __ldg(p1 + off);
            float x2 = v2 ? __ldg(p2 + off) : 0.f;

            const float4* wsp = (const float4*)(ws1 + i * 12);
            float4 u0 = wsp[0];   // j=0, k0..k3
            float4 u1 = wsp[1];   // j=1
            float4 u2 = wsp[2];   // j=2

            a0 = fmaf(x0, u0.x, a0); a0 = fmaf(x1, u1.x, a0); a0 = fmaf(x2, u2.x, a0);
            a1 = fmaf(x0, u0.y, a1); a1 = fmaf(x1, u1.y, a1); a1 = fmaf(x2, u2.y, a1);
            a2 = fmaf(x0, u0.z, a2); a2 = fmaf(x1, u1.z, a2); a2 = fmaf(x2, u2.z, a2);
            a3 = fmaf(x0, u0.w, a3); a3 = fmaf(x1, u1.w, a3); a3 = fmaf(x2, u2.w, a3);
        }
        const int yb = o * 15 + w;
        ys[0 * 120 + yb] = a0;
        ys[1 * 120 + yb] = a1;
        ys[2 * 120 + yb] = a2;
        ys[3 * 120 + yb] = a3;
    }
    __syncthreads();

    // ---- stage 2: thread (i2, kl2) computes full 14-w output row ----
    float acc[14];
    #pragma unroll
    for (int w = 0; w < 14; w++) acc[w] = 0.f;

    #pragma unroll
    for (int o = 0; o < 8; o++) {
        float yr[14];
        #pragma unroll
        for (int w = 0; w < 14; w++) yr[w] = ys[kl2 * 120 + o * 15 + w];
        const float wa = wr[o * 3 + 0];
        const float wb = wr[o * 3 + 1];
        const float wc = wr[o * 3 + 2];
        #pragma unroll
        for (int w = 0; w < 14; w++) {
            acc[w] = fmaf(yr[w], wb, acc[w]);
            if (w > 0)  acc[w] = fmaf(yr[w - 1], wa, acc[w]);
            if (w < 13) acc[w] = fmaf(yr[w + 1], wc, acc[w]);
        }
    }

    float* op = out + (i2 * 16 + kq * 4 + kl2) * 196 + h * 14;
    #pragma unroll
    for (int w = 0; w < 14; w++) op[w] = acc[w];
}

extern "C" void kernel_launch(void* const* d_in, const int* in_sizes, int n_in,
                              void* d_out, int out_size)
{
    const float* x  = (const float*)d_in[0];   // (1,512,14,14)
    const float* w1 = (const float*)d_in[1];   // (16,64,3)
    const float* w2 = (const float*)d_in[2];   // (32,8,3)
    float* out = (float*)d_out;                // (1,512,14,14)

    fused_kernel<<<dim3(4, 14), 128>>>(x, w1, w2, out);
}

// round 3
// speedup vs baseline: 1.3432x; 1.3432x over previous
#include <cuda_runtime.h>

// Fused shift + grouped conv(H taps, w1) + grouped conv(W taps, w2).
//
// x:  (1,512,14,14) fp32, channel c = i*8 + o   (i=0..63, o=0..7)
// Stage 1: y[k,o,h,w] = sum_{i,j} x[(h+j-2) mod 14][..] * w1[k,i,j],
//          tap j valid iff 0 <= h+j-1 < 14  (roll +1 along H, then zero-pad).
// Stage 2: out[(i2*16+k)*196 + h*14 + w] = sum_{o,t} y[k,o,h,w-1+t] * w2[i2,o,t]
//          (zero pad along W).
//
// Grid (16 k, 14 h) = 224 CTAs, 224 threads.
// Stage-1 thread = (g in 0..3 splits i, o in 0..7, wp in 0..6 covers w-pair).
// Stage-2 thread = (i2 in 0..31, wp in 0..6).

__global__ void __launch_bounds__(224) fused_kernel(
    const float* __restrict__ x,
    const float* __restrict__ w1,
    const float* __restrict__ w2,
    float* __restrict__ out)
{
    __shared__ float ws1[192];                    // w1[k][i][j], this CTA's k
    __shared__ float ws2[768];                    // all of w2
    __shared__ __align__(16) float part[112 * 4]; // [(o*14+w)*4 + g]
    __shared__ float ys[8 * 16];                  // y[o][w], row pad to 16

    const int k   = blockIdx.x;   // 0..15
    const int h   = blockIdx.y;   // 0..13
    const int tid = threadIdx.x;  // 0..223

    // ---- stage weights into smem ----
    if (tid < 192) ws1[tid] = __ldg(w1 + k * 192 + tid);
    for (int idx = tid; idx < 768; idx += 224) ws2[idx] = __ldg(w2 + idx);

    // ---- stage-1 thread decode ----
    const int g   = tid / 56;          // 0..3  (i-split)
    const int rem = tid - g * 56;
    const int o   = rem / 7;           // 0..7
    const int wp  = rem - o * 7;       // 0..6  -> w0 = 2*wp
    const int w0  = wp * 2;

    // taps: source rows (mod-14 roll) and validity
    const int  r0 = (h + 12) % 14;     // j=0, valid iff h >= 1
    const int  r1 = (h + 13) % 14;     // j=1, always valid
    const int  r2 = h;                 // j=2, valid iff h <= 12
    const bool v0 = (h >= 1);
    const bool v2 = (h <= 12);

    const float2* __restrict__ px = (const float2*)x;
    // float2 index of x[(i*8+o)*196 + r*14 + w0] = (i*8+o)*98 + r*7 + wp
    const int e0 = o * 98 + r0 * 7 + wp;
    const int e1 = o * 98 + r1 * 7 + wp;
    const int e2 = o * 98 + r2 * 7 + wp;

    const float2 z2 = make_float2(0.f, 0.f);
    float accA = 0.f, accB = 0.f;      // w0 and w0+1

    const int ib = g * 16;
    #pragma unroll
    for (int ii = 0; ii < 16; ii++) {
        const int i   = ib + ii;
        const int off = i * 784;       // i*8*98
        float2 x0 = v0 ? __ldg(px + off + e0) : z2;
        float2 x1 =      __ldg(px + off + e1);
        float2 x2 = v2 ? __ldg(px + off + e2) : z2;
        const float wa = ws1[i * 3 + 0];
        const float wb = ws1[i * 3 + 1];
        const float wc = ws1[i * 3 + 2];
        accA = fmaf(x0.x, wa, accA);
        accA = fmaf(x1.x, wb, accA);
        accA = fmaf(x2.x, wc, accA);
        accB = fmaf(x0.y, wa, accB);
        accB = fmaf(x1.y, wb, accB);
        accB = fmaf(x2.y, wc, accB);
    }
    part[(o * 14 + w0) * 4 + g]     = accA;
    part[(o * 14 + w0 + 1) * 4 + g] = accB;
    __syncthreads();

    // ---- reduce the 4 i-partials per (o,w) ----
    if (tid < 112) {
        float4 p = *(const float4*)(part + tid * 4);
        const int oo = tid / 14;
        const int ww = tid - oo * 14;
        ys[oo * 16 + ww] = (p.x + p.y) + (p.z + p.w);
    }
    __syncthreads();

    // ---- stage 2: thread = (i2, wp), two w outputs ----
    const int i2  = tid / 7;           // 0..31
    const int wp2 = tid - i2 * 7;      // 0..6
    const int u0  = wp2 * 2;           // w = u0, u0+1

    float acc0 = 0.f, acc1 = 0.f;
    #pragma unroll
    for (int oo = 0; oo < 8; oo++) {
        const float ym1 = (u0 > 0)  ? ys[oo * 16 + u0 - 1] : 0.f;
        const float yc0 =             ys[oo * 16 + u0];
        const float yc1 =             ys[oo * 16 + u0 + 1];
        const float yp2 = (u0 < 12) ? ys[oo * 16 + u0 + 2] : 0.f;
        const float wa = ws2[(i2 * 8 + oo) * 3 + 0];
        const float wb = ws2[(i2 * 8 + oo) * 3 + 1];
        const float wc = ws2[(i2 * 8 + oo) * 3 + 2];
        acc0 = fmaf(ym1, wa, acc0);
        acc0 = fmaf(yc0, wb, acc0);
        acc0 = fmaf(yc1, wc, acc0);
        acc1 = fmaf(yc0, wa, acc1);
        acc1 = fmaf(yc1, wb, acc1);
        acc1 = fmaf(yp2, wc, acc1);
    }

    float2* po = (float2*)(out + (i2 * 16 + k) * 196 + h * 14 + u0);
    *po = make_float2(acc0, acc1);
}

extern "C" void kernel_launch(void* const* d_in, const int* in_sizes, int n_in,
                              void* d_out, int out_size)
{
    const float* x  = (const float*)d_in[0];   // (1,512,14,14)
    const float* w1 = (const float*)d_in[1];   // (16,64,3)
    const float* w2 = (const float*)d_in[2];   // (32,8,3)
    float* out = (float*)d_out;                // (1,512,14,14)

    fused_kernel<<<dim3(16, 14), 224>>>(x, w1, w2, out);
}

// round 5
// speedup vs baseline: 1.4854x; 1.1058x over previous
#include <cuda_runtime.h>

// Fused shift + grouped conv(H taps, w1) + grouped conv(W taps, w2).
//
// x:  (1,512,14,14) fp32, channel c = i*8 + o   (i=0..63, o=0..7)
// Stage 1: y[k,o,h,w] = sum_{i,j} x[(h+j-2) mod 14][..] * w1[k,i,j],
//          tap j valid iff 0 <= h+j-1 < 14  (roll +1 along H, then zero-pad).
// Stage 2: out[(i2*16+k)*196 + h*14 + w] = sum_{o,t} y[k,o,h,w-1+t] * w2[i2,o,t]
//          (zero pad along W).
//
// Grid (16 k, 14 h) = 224 CTAs, 448 threads (14 warps).
// Stage-1 thread = (g in 0..7 splits i 8-ways, o in 0..7, wp in 0..6 -> w-pair).
// Stage-2 thread = (i2 in 0..31, wp in 0..6), first 224 threads.
//
// Ordering: x loads are issued into registers BEFORE the weight-staging
// barrier (addresses independent of ws1), so the barrier + staging hides the
// global-load latency. ws1 is only read AFTER __syncthreads (round-4 race fix).

__global__ void __launch_bounds__(448) fused_kernel(
    const float* __restrict__ x,
    const float* __restrict__ w1,
    const float* __restrict__ w2,
    float* __restrict__ out)
{
    __shared__ float ws1[192];                    // w1[k][i][j], this CTA's k
    __shared__ float ws2[768];                    // all of w2
    __shared__ __align__(16) float part[112 * 8]; // [(o*14+w)*8 + g]
    __shared__ float ys[8 * 16];                  // y[o][w], row pad to 16

    const int k   = blockIdx.x;   // 0..15
    const int h   = blockIdx.y;   // 0..13
    const int tid = threadIdx.x;  // 0..447

    // ---- issue weight staging (STS lands before the barrier) ----
    if (tid < 192) ws1[tid] = __ldg(w1 + k * 192 + tid);
    for (int idx = tid; idx < 768; idx += 448) ws2[idx] = __ldg(w2 + idx);

    // ---- stage-1 thread decode ----
    const int g   = tid / 56;          // 0..7  (i-split)
    const int rem = tid - g * 56;
    const int o   = rem / 7;           // 0..7
    const int wp  = rem - o * 7;       // 0..6  -> w0 = 2*wp
    const int w0  = wp * 2;

    // taps: source rows (mod-14 roll) and validity
    const int  r0 = (h + 12) % 14;     // j=0, valid iff h >= 1
    const int  r1 = (h + 13) % 14;     // j=1, always valid
    const int  r2 = h;                 // j=2, valid iff h <= 12
    const bool v0 = (h >= 1);
    const bool v2 = (h <= 12);

    const float2* __restrict__ px = (const float2*)x;
    // float2 index of x[(i*8+o)*196 + r*14 + w0] = (i*8+o)*98 + r*7 + wp
    const int e0 = o * 98 + r0 * 7 + wp;
    const int e1 = o * 98 + r1 * 7 + wp;
    const int e2 = o * 98 + r2 * 7 + wp;

    const float2 z2 = make_float2(0.f, 0.f);
    const int ib = g * 8;

    // ---- front-batch all 24 x loads (independent of ws1) ----
    float2 xv0[8], xv1[8], xv2[8];
    #pragma unroll
    for (int ii = 0; ii < 8; ii++) {
        const int off = (ib + ii) * 784;   // i*8*98
        xv0[ii] = v0 ? __ldg(px + off + e0) : z2;
        xv1[ii] =      __ldg(px + off + e1);
        xv2[ii] = v2 ? __ldg(px + off + e2) : z2;
    }

    __syncthreads();   // ws1/ws2 visible; also hides the x-load latency

    // ---- stage 1 FMAs ----
    float accA = 0.f, accB = 0.f;      // w0 and w0+1
    #pragma unroll
    for (int ii = 0; ii < 8; ii++) {
        const int i = ib + ii;
        const float wa = ws1[i * 3 + 0];
        const float wb = ws1[i * 3 + 1];
        const float wc = ws1[i * 3 + 2];
        accA = fmaf(xv0[ii].x, wa, accA);
        accA = fmaf(xv1[ii].x, wb, accA);
        accA = fmaf(xv2[ii].x, wc, accA);
        accB = fmaf(xv0[ii].y, wa, accB);
        accB = fmaf(xv1[ii].y, wb, accB);
        accB = fmaf(xv2[ii].y, wc, accB);
    }
    part[(o * 14 + w0) * 8 + g]     = accA;
    part[(o * 14 + w0 + 1) * 8 + g] = accB;
    __syncthreads();

    // ---- reduce the 8 i-partials per (o,w) ----
    if (tid < 112) {
        const float4* pp = (const float4*)(part + tid * 8);
        float4 a = pp[0];
        float4 b = pp[1];
        const int oo = tid / 14;
        const int ww = tid - oo * 14;
        ys[oo * 16 + ww] = ((a.x + a.y) + (a.z + a.w)) +
                           ((b.x + b.y) + (b.z + b.w));
    }
    __syncthreads();

    // ---- stage 2: thread = (i2, wp), two w outputs (first 224 threads) ----
    if (tid < 224) {
        const int i2  = tid / 7;           // 0..31
        const int wp2 = tid - i2 * 7;      // 0..6
        const int u0  = wp2 * 2;           // w = u0, u0+1

        float acc0 = 0.f, acc1 = 0.f;
        #pragma unroll
        for (int oo = 0; oo < 8; oo++) {
            const float ym1 = (u0 > 0)  ? ys[oo * 16 + u0 - 1] : 0.f;
            const float yc0 =             ys[oo * 16 + u0];
            const float yc1 =             ys[oo * 16 + u0 + 1];
            const float yp2 = (u0 < 12) ? ys[oo * 16 + u0 + 2] : 0.f;
            const float wa = ws2[(i2 * 8 + oo) * 3 + 0];
            const float wb = ws2[(i2 * 8 + oo) * 3 + 1];
            const float wc = ws2[(i2 * 8 + oo) * 3 + 2];
            acc0 = fmaf(ym1, wa, acc0);
            acc0 = fmaf(yc0, wb, acc0);
            acc0 = fmaf(yc1, wc, acc0);
            acc1 = fmaf(yc0, wa, acc1);
            acc1 = fmaf(yc1, wb, acc1);
            acc1 = fmaf(yp2, wc, acc1);
        }

        float2* po = (float2*)(out + (i2 * 16 + k) * 196 + h * 14 + u0);
        *po = make_float2(acc0, acc1);
    }
}

extern "C" void kernel_launch(void* const* d_in, const int* in_sizes, int n_in,
                              void* d_out, int out_size)
{
    const float* x  = (const float*)d_in[0];   // (1,512,14,14)
    const float* w1 = (const float*)d_in[1];   // (16,64,3)
    const float* w2 = (const float*)d_in[2];   // (32,8,3)
    float* out = (float*)d_out;                // (1,512,14,14)

    fused_kernel<<<dim3(16, 14), 448>>>(x, w1, w2, out);
}

// round 6
// speedup vs baseline: 1.5018x; 1.0111x over previous
#include <cuda_runtime.h>

// Fused shift + grouped conv(H taps, w1) + grouped conv(W taps, w2).
//
// x:  (1,512,14,14) fp32, channel c = i*8 + o   (i=0..63, o=0..7)
// Stage 1: y[k,o,h,w] = sum_{i,j} x[(h+j-2) mod 14][..] * w1[k,i,j],
//          tap j valid iff 0 <= h+j-1 < 14  (roll +1 along H, zero-pad).
//          Loads are ALWAYS issued (mod-14 row is in-bounds); invalid taps are
//          neutralized by zeroing the weight (v0/v2 are CTA-uniform).
// Stage 2: out[(i2*16+k)*196 + h*14 + w] = sum_{o,t} y[k,o,h,w-1+t] * w2[i2,o,t]
//
// Grid (16 k, 14 h) = 224 CTAs, 448 threads (14 warps).
// Stage-1 thread = (g 0..7 splits i, o 0..7, wp 0..6 -> w-pair).
// x loads are volatile-asm front-batched BEFORE the weight barrier so the
// barrier hides the L2 round trip (ptxas cannot sink volatile loads).

__device__ __forceinline__ float2 ldg64v(const float2* p) {
    float2 v;
    asm volatile("ld.global.nc.v2.f32 {%0,%1},[%2];"
                 : "=f"(v.x), "=f"(v.y) : "l"(p));
    return v;
}

__global__ void __launch_bounds__(448, 1) fused_kernel(
    const float* __restrict__ x,
    const float* __restrict__ w1,
    const float* __restrict__ w2,
    float* __restrict__ out)
{
    __shared__ float ws1[192];                 // w1[k][i][j], this CTA's k
    __shared__ float ws2[768];                 // all of w2
    __shared__ float part[8 * 8 * 16];         // [g][o][w pad 16]
    __shared__ float ys[8 * 16];               // y[o][w], row pad to 16

    const int k   = blockIdx.x;   // 0..15
    const int h   = blockIdx.y;   // 0..13
    const int tid = threadIdx.x;  // 0..447

    // ---- stage-1 thread decode ----
    const int g   = tid / 56;          // 0..7  (i-split)
    const int rem = tid - g * 56;
    const int o   = rem / 7;           // 0..7
    const int wp  = rem - o * 7;       // 0..6  -> w0 = 2*wp
    const int w0  = wp * 2;

    // taps: source rows (mod-14 roll); always in-bounds
    const int  r0 = (h + 12) % 14;     // j=0, contributes iff h >= 1
    const int  r1 = (h + 13) % 14;     // j=1, always
    const int  r2 = h;                 // j=2, contributes iff h <= 12
    const bool v0 = (h >= 1);
    const bool v2 = (h <= 12);

    const float2* __restrict__ px = (const float2*)x;
    // float2 index of x[(i*8+o)*196 + r*14 + w0] = (i*8+o)*98 + r*7 + wp
    const int e0 = o * 98 + r0 * 7 + wp;
    const int e1 = o * 98 + r1 * 7 + wp;
    const int e2 = o * 98 + r2 * 7 + wp;
    const int ib = g * 8;

    // ---- front-batch all 24 x loads (volatile: cannot sink past barrier) ----
    float2 xv0[8], xv1[8], xv2[8];
    #pragma unroll
    for (int ii = 0; ii < 8; ii++) {
        const int off = (ib + ii) * 784;   // i*8*98
        xv0[ii] = ldg64v(px + off + e0);
        xv1[ii] = ldg64v(px + off + e1);
        xv2[ii] = ldg64v(px + off + e2);
    }

    // ---- weight staging (latency overlaps the x loads above) ----
    if (tid < 192) ws1[tid] = __ldg(w1 + k * 192 + tid);
    for (int idx = tid; idx < 768; idx += 448) ws2[idx] = __ldg(w2 + idx);

    __syncthreads();   // ws1/ws2 visible; x loads in flight behind it

    // ---- stage 1 FMAs ----
    float accA = 0.f, accB = 0.f;      // w0 and w0+1
    #pragma unroll
    for (int ii = 0; ii < 8; ii++) {
        const int i = ib + ii;
        const float wa = v0 ? ws1[i * 3 + 0] : 0.f;
        const float wb =      ws1[i * 3 + 1];
        const float wc = v2 ? ws1[i * 3 + 2] : 0.f;
        accA = fmaf(xv0[ii].x, wa, accA);
        accA = fmaf(xv1[ii].x, wb, accA);
        accA = fmaf(xv2[ii].x, wc, accA);
        accB = fmaf(xv0[ii].y, wa, accB);
        accB = fmaf(xv1[ii].y, wb, accB);
        accB = fmaf(xv2[ii].y, wc, accB);
    }
    part[g * 128 + o * 16 + w0]     = accA;
    part[g * 128 + o * 16 + w0 + 1] = accB;
    __syncthreads();

    // ---- reduce the 8 i-partials per (o,w) ----
    if (tid < 112) {
        const int oo = tid / 14;
        const int ww = tid - oo * 14;
        const int b  = oo * 16 + ww;
        float s0 = part[0 * 128 + b] + part[1 * 128 + b];
        float s1 = part[2 * 128 + b] + part[3 * 128 + b];
        float s2 = part[4 * 128 + b] + part[5 * 128 + b];
        float s3 = part[6 * 128 + b] + part[7 * 128 + b];
        ys[b] = (s0 + s1) + (s2 + s3);
    }
    __syncthreads();

    // ---- stage 2: thread = (i2, wp), two w outputs (first 224 threads) ----
    if (tid < 224) {
        const int i2  = tid / 7;           // 0..31
        const int wp2 = tid - i2 * 7;      // 0..6
        const int u0  = wp2 * 2;           // w = u0, u0+1

        float acc0 = 0.f, acc1 = 0.f;
        #pragma unroll
        for (int oo = 0; oo < 8; oo++) {
            const float ym1 = (u0 > 0)  ? ys[oo * 16 + u0 - 1] : 0.f;
            const float yc0 =             ys[oo * 16 + u0];
            const float yc1 =             ys[oo * 16 + u0 + 1];
            const float yp2 = (u0 < 12) ? ys[oo * 16 + u0 + 2] : 0.f;
            const float wa = ws2[(i2 * 8 + oo) * 3 + 0];
            const float wb = ws2[(i2 * 8 + oo) * 3 + 1];
            const float wc = ws2[(i2 * 8 + oo) * 3 + 2];
            acc0 = fmaf(ym1, wa, acc0);
            acc0 = fmaf(yc0, wb, acc0);
            acc0 = fmaf(yc1, wc, acc0);
            acc1 = fmaf(yc0, wa, acc1);
            acc1 = fmaf(yc1, wb, acc1);
            acc1 = fmaf(yp2, wc, acc1);
        }

        float2* po = (float2*)(out + (i2 * 16 + k) * 196 + h * 14 + u0);
        *po = make_float2(acc0, acc1);
    }
}

extern "C" void kernel_launch(void* const* d_in, const int* in_sizes, int n_in,
                              void* d_out, int out_size)
{
    const float* x  = (const float*)d_in[0];   // (1,512,14,14)
    const float* w1 = (const float*)d_in[1];   // (16,64,3)
    const float* w2 = (const float*)d_in[2];   // (32,8,3)
    float* out = (float*)d_out;                // (1,512,14,14)

    fused_kernel<<<dim3(16, 14), 448>>>(x, w1, w2, out);
}